// round 13
// baseline (speedup 1.0000x reference)
#include <cuda_runtime.h>
#include <cuda_bf16.h>
#include <cstdint>

#define BB 8
#define NN 2048
#define DD 128
#define LL 3
#define ALPHA 0.2f
#define NEG_INF -9e15f
#define NW 64  /* 32-bit words per adjacency row (N/32) */

// Scratch (device globals: no allocation allowed in kernel_launch)
__device__ __align__(16) __nv_bfloat16  g_hT[BB * DD * NN];   // 4 MB bf16 h^T
__device__ float    g_s1[BB * NN];
__device__ float    g_s2[BB * NN];
__device__ float    g_mb[BB];                                 // per-batch max s2
__device__ unsigned g_bits[BB * NN * NW];                     // 4 MB packed adj

// ======================= helpers ============================
__device__ __forceinline__ uint32_t smem_u32(const void* p) {
    uint32_t a;
    asm("{ .reg .u64 t; cvta.to.shared.u64 t, %1; cvt.u32.u64 %0, t; }"
        : "=r"(a) : "l"(p));
    return a;
}
__device__ __forceinline__ void sts128(uint32_t a, uint32_t x, uint32_t y,
                                       uint32_t z, uint32_t w) {
    asm volatile("st.shared.v4.b32 [%0], {%1,%2,%3,%4};"
                 :: "r"(a), "r"(x), "r"(y), "r"(z), "r"(w) : "memory");
}
__device__ __forceinline__ uint32_t bf16pack(float lo, float hi) {
    uint32_t r;
    asm("cvt.rn.bf16x2.f32 %0, %1, %2;" : "=r"(r) : "f"(hi), "f"(lo));
    return r;
}
__device__ __forceinline__ void ldsm4(uint32_t* r, uint32_t a) {
    asm volatile("ldmatrix.sync.aligned.m8n8.x4.shared.b16 {%0,%1,%2,%3}, [%4];"
                 : "=r"(r[0]), "=r"(r[1]), "=r"(r[2]), "=r"(r[3]) : "r"(a));
}
__device__ __forceinline__ void mma16816(float* c, const uint32_t* a,
                                         uint32_t b0, uint32_t b1) {
    asm volatile("mma.sync.aligned.m16n8k16.row.col.f32.bf16.bf16.f32 "
                 "{%0,%1,%2,%3}, {%4,%5,%6,%7}, {%8,%9}, {%0,%1,%2,%3};"
                 : "+f"(c[0]), "+f"(c[1]), "+f"(c[2]), "+f"(c[3])
                 : "r"(a[0]), "r"(a[1]), "r"(a[2]), "r"(a[3]),
                   "r"(b0), "r"(b1));
}

// ---------------------------------------------------------------------------
// K0: pack adj into bitmask. 8 elems/thread (2x int4), byte-shuffle assembly.
// ---------------------------------------------------------------------------
__global__ __launch_bounds__(256) void pack_adj_kernel(const int4* __restrict__ adj4)
{
    int tid = blockIdx.x * 256 + threadIdx.x;     // handles elems 8*tid..+7
    int4 v0 = adj4[2 * tid];
    int4 v1 = adj4[2 * tid + 1];
    unsigned byte =
        (unsigned)(v0.x > 0)        | ((unsigned)(v0.y > 0) << 1) |
        ((unsigned)(v0.z > 0) << 2) | ((unsigned)(v0.w > 0) << 3) |
        ((unsigned)(v1.x > 0) << 4) | ((unsigned)(v1.y > 0) << 5) |
        ((unsigned)(v1.z > 0) << 6) | ((unsigned)(v1.w > 0) << 7);
    unsigned val = byte << (8 * (threadIdx.x & 3));
    val |= __shfl_xor_sync(0xffffffffu, val, 1);
    val |= __shfl_xor_sync(0xffffffffu, val, 2);
    if ((threadIdx.x & 3) == 0) g_bits[tid >> 2] = val;
}

// ---------------------------------------------------------------------------
// K1: h = relu(x @ W + b); s1 = h.a1; s2 = h.a2; writes bf16 h^T directly.
// ---------------------------------------------------------------------------
#define HSP 72   /* hstage pitch in bf16: 144 bytes, 16B-aligned rows */

__global__ __launch_bounds__(256) void gemm_h_kernel(
    const float* __restrict__ x, const float* __restrict__ Wg,
    const float* __restrict__ bg, const float* __restrict__ aa, int layer)
{
    __shared__ float x_s[64][33];
    __shared__ float W_s[32][128];
    __shared__ __align__(16) __nv_bfloat16 hstage[128][HSP]; // [d][row_local]

    const float* W    = Wg + layer * DD * DD;
    const float* bias = bg + layer * DD;
    const float* a1   = aa + layer * 2 * DD;
    const float* a2   = a1 + DD;

    int t   = threadIdx.x;
    int tr  = t >> 4;
    int tc  = t & 15;
    int row0 = blockIdx.x * 64;
    int batch = row0 >> 11;
    int jloc  = row0 & (NN - 1);

    float acc[4][8];
#pragma unroll
    for (int i = 0; i < 4; i++)
#pragma unroll
        for (int u = 0; u < 8; u++) acc[i][u] = 0.f;

    for (int kc = 0; kc < 4; kc++) {
        __syncthreads();
        {
            int r = t >> 2, q = t & 3;
            const float4* src = (const float4*)(x + (size_t)(row0 + r) * DD + kc * 32 + q * 8);
            float4 v0 = src[0], v1 = src[1];
            float* dst = &x_s[r][q * 8];
            dst[0] = v0.x; dst[1] = v0.y; dst[2] = v0.z; dst[3] = v0.w;
            dst[4] = v1.x; dst[5] = v1.y; dst[6] = v1.z; dst[7] = v1.w;
        }
#pragma unroll
        for (int p = 0; p < 4; p++) {
            int i = t + 256 * p;
            int k = i >> 5, dq = (i & 31) * 4;
            *(float4*)&W_s[k][dq] = *(const float4*)(W + (size_t)(kc * 32 + k) * DD + dq);
        }
        __syncthreads();
#pragma unroll
        for (int k = 0; k < 32; k++) {
            float xv[4], wv[8];
#pragma unroll
            for (int i = 0; i < 4; i++) xv[i] = x_s[tr * 4 + i][k];
#pragma unroll
            for (int u = 0; u < 8; u++) wv[u] = W_s[k][tc + (u << 4)];
#pragma unroll
            for (int i = 0; i < 4; i++)
#pragma unroll
                for (int u = 0; u < 8; u++)
                    acc[i][u] = fmaf(xv[i], wv[u], acc[i][u]);
        }
    }

    float bv[8], a1v[8], a2v[8];
#pragma unroll
    for (int u = 0; u < 8; u++) {
        int d = tc + (u << 4);
        bv[u] = bias[d]; a1v[u] = a1[d]; a2v[u] = a2[d];
    }
    float hv[4][8];
#pragma unroll
    for (int i = 0; i < 4; i++)
#pragma unroll
        for (int u = 0; u < 8; u++)
            hv[i][u] = fmaxf(acc[i][u] + bv[u], 0.f);

    // s1/s2 row reductions
#pragma unroll
    for (int i = 0; i < 4; i++) {
        int row = row0 + tr * 4 + i;
        float p1 = 0.f, p2 = 0.f;
#pragma unroll
        for (int u = 0; u < 8; u++) {
            p1 = fmaf(hv[i][u], a1v[u], p1);
            p2 = fmaf(hv[i][u], a2v[u], p2);
        }
#pragma unroll
        for (int off = 8; off; off >>= 1) {
            p1 += __shfl_xor_sync(0xffffffffu, p1, off, 16);
            p2 += __shfl_xor_sync(0xffffffffu, p2, off, 16);
        }
        if (tc == 0) { g_s1[row] = p1; g_s2[row] = p2; }
    }

    // stage bf16 transposed: hstage[d][row_local]
#pragma unroll
    for (int u = 0; u < 8; u++) {
        uint32_t lo = bf16pack(hv[0][u], hv[1][u]);
        uint32_t hi = bf16pack(hv[2][u], hv[3][u]);
        uint2 pkt; pkt.x = lo; pkt.y = hi;
        *(uint2*)&hstage[tc + (u << 4)][tr * 4] = pkt;
    }
    __syncthreads();

    // write out: thread t -> d = t>>1, 32 contiguous j
    {
        int d = t >> 1, half = t & 1;
        const uint4* src = (const uint4*)&hstage[d][half * 32];
        uint4 v0 = src[0], v1 = src[1], v2 = src[2], v3 = src[3];
        uint4* dst = (uint4*)(g_hT + (size_t)batch * DD * NN + (size_t)d * NN
                              + jloc + half * 32);
        dst[0] = v0; dst[1] = v1; dst[2] = v2; dst[3] = v3;
    }
}

// ---------------------------------------------------------------------------
// K2: per-batch max of s2 (any upper bound works; ratios invariant to shift).
// ---------------------------------------------------------------------------
__global__ __launch_bounds__(256) void batchmax_kernel()
{
    __shared__ float red[8];
    int b = blockIdx.x, t = threadIdx.x;
    const float* s2 = g_s2 + (b << 11);
    float mx = -3.0e38f;
#pragma unroll
    for (int k = 0; k < 8; k++) mx = fmaxf(mx, s2[t + 256 * k]);
#pragma unroll
    for (int off = 16; off; off >>= 1)
        mx = fmaxf(mx, __shfl_xor_sync(0xffffffffu, mx, off));
    if ((t & 31) == 0) red[t >> 5] = mx;
    __syncthreads();
    if (t == 0) {
        float m = red[0];
#pragma unroll
        for (int k = 1; k < 8; k++) m = fmaxf(m, red[k]);
        g_mb[b] = m;
    }
}

// ---------------------------------------------------------------------------
// K3: HMMA fused masked-softmax @ h + residual.
// CTA: 64 rows x 128 d, grid 256 -> 2 CTAs/SM (phase overlap across CTAs).
// 8 warps in 4x2 grid, warp tile 16 rows x 64 cols. Double-buffered A/B,
// one barrier per 32-j chunk. ~32 acc regs/thread -> fits 2 CTAs/SM.
// ---------------------------------------------------------------------------
#define PITCHB 80                /* 32 bf16 + 16B pad: ldsm conflict-free */
#define ATILE  (64 * PITCHB)     /* 5120 B  */
#define BTILE  (128 * PITCHB)    /* 10240 B */

__global__ __launch_bounds__(256, 2) void attn_kernel(
    const float* __restrict__ xin, float* __restrict__ xout)
{
    __shared__ __align__(16) char A_s[2 * ATILE];    // A0 A1
    __shared__ __align__(16) char B_s[2 * BTILE];    // B0 B1
    __shared__ float zbuf[256];
    __shared__ float zi[64];

    int t = threadIdx.x, lane = t & 31, w = t >> 5;
    int wr = w >> 1, wc = w & 1;          // 4x2 warp grid
    int batch = blockIdx.y;
    int row0  = blockIdx.x * 64;
    int grow0 = (batch << 11) + row0;

    // P-gen mapping: row = t>>2 (0..63), 8 j per thread at jq*8
    int prow = t >> 2, jq = t & 3;
    float s1v = g_s1[grow0 + prow];
    float mbv = g_mb[batch];
    float me  = s1v + mbv;
    float mv  = (me > 0.f) ? me : ALPHA * me;   // lrelu(s1 + max s2) >= all e
    const unsigned* bitrow = g_bits + (size_t)(grow0 + prow) * NW;
    const float* s2B = g_s2 + (batch << 11);
    // H-tile mapping: d = t>>1 (0..127), 16B-half = t&1
    int hd = t >> 1, hh = t & 1;
    const __nv_bfloat16* hsrc =
        g_hT + (size_t)batch * DD * NN + (size_t)hd * NN + hh * 16;

    uint32_t aA = smem_u32(A_s), aB = smem_u32(B_s);
    uint32_t stA = aA + (uint32_t)(prow * PITCHB + jq * 16);
    uint32_t stB = aB + (uint32_t)(hd * PITCHB + hh * 32);
    uint32_t lmA = aA + (uint32_t)(wr * 16 + (lane & 15)) * PITCHB
                      + ((lane >> 4) & 1) * 16;
    uint32_t lmB = aB + (uint32_t)(wc * 64 + (lane & 15)) * PITCHB
                      + ((lane >> 4) & 1) * 16;

    float acc[8][4];
#pragma unroll
    for (int n = 0; n < 8; n++)
#pragma unroll
        for (int q = 0; q < 4; q++) acc[n][q] = 0.f;
    float zpart = 0.f;

    // prefetch chunk 0
    uint4  hp0 = *(const uint4*)(hsrc);
    uint4  hp1 = *(const uint4*)(hsrc + 8);
    float4 sp0 = *(const float4*)(s2B + jq * 8);
    float4 sp1 = *(const float4*)(s2B + jq * 8 + 4);
    unsigned wp = bitrow[0];

    for (int i = 0; i < 64; i++) {
        uint32_t offA = (uint32_t)(i & 1) * ATILE;
        uint32_t offB = (uint32_t)(i & 1) * BTILE;
        // ---- store H tile (32B per thread) ----
        sts128(stB + offB,      hp0.x, hp0.y, hp0.z, hp0.w);
        sts128(stB + offB + 16, hp1.x, hp1.y, hp1.z, hp1.w);
        // ---- compute + store P tile (8 exp per thread) ----
        {
            float sv[8] = { sp0.x, sp0.y, sp0.z, sp0.w,
                            sp1.x, sp1.y, sp1.z, sp1.w };
            float ww[8];
#pragma unroll
            for (int k = 0; k < 8; k++) {
                float e = s1v + sv[k];
                e = (e > 0.f) ? e : ALPHA * e;
                if (!((wp >> (jq * 8 + k)) & 1u)) e = NEG_INF;
                float v = __expf(e - mv);   // masked -> 0
                zpart += v;
                ww[k] = v;
            }
            sts128(stA + offA, bf16pack(ww[0], ww[1]), bf16pack(ww[2], ww[3]),
                               bf16pack(ww[4], ww[5]), bf16pack(ww[6], ww[7]));
        }
        // ---- prefetch chunk i+1 ----
        {
            int inext = (i < 63) ? i + 1 : 63;
            const __nv_bfloat16* hn = hsrc + inext * 32;
            hp0 = *(const uint4*)(hn);
            hp1 = *(const uint4*)(hn + 8);
            sp0 = *(const float4*)(s2B + inext * 32 + jq * 8);
            sp1 = *(const float4*)(s2B + inext * 32 + jq * 8 + 4);
            wp = bitrow[inext];
        }
        __syncthreads();   // buf(i) ready; prior reads of this buf done
        // ---- mma: warp tile 16 rows x 64 cols ----
#pragma unroll
        for (int ks = 0; ks < 2; ks++) {
            uint32_t a[4];
            ldsm4(a, lmA + offA + ks * 32);
#pragma unroll
            for (int g = 0; g < 4; g++) {
                uint32_t b[4];
                ldsm4(b, lmB + offB + g * 16 * PITCHB + ks * 32);
                mma16816(acc[2 * g],     a, b[0], b[2]);
                mma16816(acc[2 * g + 1], a, b[1], b[3]);
            }
        }
    }

    // ---- Z reduction: 4 partials per row ----
    zbuf[t] = zpart;
    __syncthreads();
    if (t < 64) {
        zi[t] = 1.0f / (zbuf[t * 4] + zbuf[t * 4 + 1]
                      + zbuf[t * 4 + 2] + zbuf[t * 4 + 3]);
    }
    __syncthreads();

    // ---- epilogue: out = x_in + acc * invZ ----
    {
        int qr = lane >> 2, qc = lane & 3;
        int r0 = wr * 16 + qr;
        float iza = zi[r0], izb = zi[r0 + 8];
        const float* i0 = xin + (size_t)(grow0 + r0) * DD + wc * 64;
        const float* i1 = i0 + 8 * DD;
        float* o0 = xout + (size_t)(grow0 + r0) * DD + wc * 64;
        float* o1 = o0 + 8 * DD;
#pragma unroll
        for (int nt = 0; nt < 8; nt++) {
            int col = nt * 8 + qc * 2;
            float2 v0 = *(const float2*)(i0 + col);
            v0.x = fmaf(acc[nt][0], iza, v0.x);
            v0.y = fmaf(acc[nt][1], iza, v0.y);
            *(float2*)(o0 + col) = v0;
            float2 v1 = *(const float2*)(i1 + col);
            v1.x = fmaf(acc[nt][2], izb, v1.x);
            v1.y = fmaf(acc[nt][3], izb, v1.y);
            *(float2*)(o1 + col) = v1;
        }
    }
}

// ---------------------------------------------------------------------------
extern "C" void kernel_launch(void* const* d_in, const int* in_sizes, int n_in,
                              void* d_out, int out_size)
{
    const float* x   = (const float*)d_in[0];
    const int*   adj = (const int*)  d_in[1];
    const float* Wg  = (const float*)d_in[2];
    const float* bg  = (const float*)d_in[3];
    const float* aa  = (const float*)d_in[4];
    float* out = (float*)d_out;

    pack_adj_kernel<<<(BB * NN * NN) / (8 * 256), 256>>>((const int4*)adj);

    for (int l = 0; l < LL; l++) {
        const float* src = (l == 0) ? x : out;
        gemm_h_kernel<<<(BB * NN) / 64, 256>>>(src, Wg, bg, aa, l);
        batchmax_kernel<<<BB, 256>>>();
        attn_kernel<<<dim3(NN / 64, BB), 256>>>(src, out);
    }
}